// round 7
// baseline (speedup 1.0000x reference)
#include <cuda_runtime.h>
#include <cuda_bf16.h>
#include <cstdint>
#include <math.h>

// Problem constants
#define BSZ   2
#define TLEN  2048
#define DM    1024
#define DI    2048
#define NST   16
#define DTR   64
#define NPROJ 96
#define MROWS (BSZ*TLEN)    // 4096
#define KSPLIT 8

#define NKC_DM (DM/64)      // 16 k-chunks for K=1024
#define NKC_DI (DI/64)      // 32 k-chunks for K=2048

// A tile: 256 rows x 64 k = 16384 els = 32KB.  B tile: 128 x 64 = 8192 els = 16KB.
#define A_TILE_ELS (256*64)
#define B_TILE_ELS (128*64)
#define STAGE_BYTES 98304            // Ah(32K) Al(32K) Bh(16K) Bl(16K)
#define OFF_AL 32768
#define OFF_BH 65536
#define OFF_BL 81920
#define TG_SMEM_BYTES (2*STAGE_BYTES) // 192KB

// ---------------------------------------------------------------------------
// Scratch (device globals; allocation-free rule). Zero-initialized at load —
// padded regions of gWxT stay zero forever.
// ---------------------------------------------------------------------------
__device__ __align__(256) float g_uz[(size_t)MROWS * 2 * DI];
__device__ __align__(256) float g_uc[(size_t)MROWS * DI];
__device__ __align__(256) float g_proj[(size_t)MROWS * NPROJ];
__device__ __align__(256) float g_projp[(size_t)KSPLIT * MROWS * NPROJ];
__device__ __align__(256) float g_delta[(size_t)MROWS * DI];

// tiled + swizzled bf16 operand arrays
__device__ __align__(256) __nv_bfloat16 gx_h[(size_t)MROWS * DM];      // [16][16][256][64]
__device__ __align__(256) __nv_bfloat16 gx_l[(size_t)MROWS * DM];
__device__ __align__(256) __nv_bfloat16 gWinT_h[(size_t)(2*DI) * DM];  // [32][16][128][64]
__device__ __align__(256) __nv_bfloat16 gWinT_l[(size_t)(2*DI) * DM];
__device__ __align__(256) __nv_bfloat16 guc_h[(size_t)MROWS * DI];     // [16][32][256][64]
__device__ __align__(256) __nv_bfloat16 guc_l[(size_t)MROWS * DI];
__device__ __align__(256) __nv_bfloat16 gWxT_h[(size_t)128 * DI];      // [1][32][128][64] (rows 96..127 zero)
__device__ __align__(256) __nv_bfloat16 gWxT_l[(size_t)128 * DI];
__device__ __align__(256) __nv_bfloat16 gy_h[(size_t)MROWS * DI];      // [16][32][256][64]
__device__ __align__(256) __nv_bfloat16 gy_l[(size_t)MROWS * DI];
__device__ __align__(256) __nv_bfloat16 gWoT_h[(size_t)DM * DI];       // [8][32][128][64]
__device__ __align__(256) __nv_bfloat16 gWoT_l[(size_t)DM * DI];

// ---------------------------------------------------------------------------
// PTX helpers (sm_90 BASELINE only — bench's ptxas target is sm_103 w/o 'a')
// ---------------------------------------------------------------------------
__device__ __forceinline__ uint32_t smem_u32(const void* p) {
    uint32_t a;
    asm("{ .reg .u64 t; cvta.to.shared.u64 t, %1; cvt.u32.u64 %0, t; }"
        : "=r"(a) : "l"(p));
    return a;
}
__device__ __forceinline__ void bulk_g2s(uint32_t dst, const void* src,
                                         uint32_t bytes, uint32_t mbar) {
    asm volatile(
        "cp.async.bulk.shared::cta.global.mbarrier::complete_tx::bytes "
        "[%0], [%1], %2, [%3];"
        :: "r"(dst), "l"(src), "r"(bytes), "r"(mbar) : "memory");
}
#define MBARRIER_INIT(mb, c) \
    asm volatile("mbarrier.init.shared.b64 [%0], %1;" :: "r"((uint32_t)(mb)), "r"((uint32_t)(c)) : "memory")
#define MBARRIER_INVAL(mb) \
    asm volatile("mbarrier.inval.shared.b64 [%0];" :: "r"((uint32_t)(mb)) : "memory")
#define MBARRIER_EXPECT_TX(mb, tx) \
    asm volatile("mbarrier.arrive.expect_tx.shared.b64 _, [%0], %1;" :: "r"((uint32_t)(mb)), "r"((uint32_t)(tx)) : "memory")

__device__ __forceinline__ void mbar_wait(uint32_t mb, uint32_t parity) {
    uint32_t done;
    asm volatile("{\n\t.reg .pred p;\n\t"
                 "mbarrier.try_wait.parity.acquire.cta.shared::cta.b64 p, [%1], %2;\n\t"
                 "selp.b32 %0, 1, 0, p;\n\t}"
                 : "=r"(done) : "r"(mb), "r"(parity) : "memory");
    if (!done) {
        asm volatile("{\n\t.reg .pred P1;\n\t"
                     "W%=:\n\t"
                     "mbarrier.try_wait.parity.acquire.cta.shared::cta.b64 P1, [%0], %1, 0x989680;\n\t"
                     "@P1 bra.uni D%=;\n\t"
                     "bra.uni W%=;\n\t"
                     "D%=:\n\t}" :: "r"(mb), "r"(parity) : "memory");
    }
}
__device__ __forceinline__ void ldmat_x4(uint32_t* r, uint32_t addr) {
    asm volatile("ldmatrix.sync.aligned.m8n8.x4.shared.b16 {%0,%1,%2,%3}, [%4];"
        : "=r"(r[0]), "=r"(r[1]), "=r"(r[2]), "=r"(r[3]) : "r"(addr));
}
__device__ __forceinline__ void mma16816(float* c, const uint32_t* a, const uint32_t* b) {
    asm volatile(
        "mma.sync.aligned.m16n8k16.row.col.f32.bf16.bf16.f32 "
        "{%0,%1,%2,%3}, {%4,%5,%6,%7}, {%8,%9}, {%0,%1,%2,%3};"
        : "+f"(c[0]), "+f"(c[1]), "+f"(c[2]), "+f"(c[3])
        : "r"(a[0]), "r"(a[1]), "r"(a[2]), "r"(a[3]), "r"(b[0]), "r"(b[1]));
}

// ---------------------------------------------------------------------------
// bf16 3-split HMMA GEMM with bulk-copy pipeline.
// CTA tile 256(M) x 128(N), BK=64, 512 threads = 16 warps (8 M x 2 N),
// warp tile 32 x 64. Double-buffered 96KB stages filled by cp.async.bulk.
// Operands come from pre-tiled pre-swizzled gmem arrays.
// ---------------------------------------------------------------------------
__global__ __launch_bounds__(512, 1) void tgemm_bulk(
    const __nv_bfloat16* __restrict__ Ah, const __nv_bfloat16* __restrict__ Al,
    const __nv_bfloat16* __restrict__ Bh, const __nv_bfloat16* __restrict__ Bl,
    float* __restrict__ C, int ldc, int Nvalid, int nkTot, int nkPer, size_t cslice)
{
    extern __shared__ char sm[];
    __shared__ uint64_t mbars[2];
    const uint32_t smb = smem_u32(sm);
    const uint32_t mb0 = smem_u32(&mbars[0]);

    const int tid = threadIdx.x;
    const int wid = tid >> 5, lane = tid & 31;
    const int wy = wid & 7, wx = wid >> 3;
    const int g = lane >> 2, q2 = (lane & 3) * 2;
    const int mTile = blockIdx.y, nTile = blockIdx.x;
    const int kcB = blockIdx.z * nkPer;
    C += (size_t)blockIdx.z * cslice;

    // per-lane fragment addressing (swizzled rows of 128B)
    const int laneA_row = (((lane >> 3) & 1) << 3) + (lane & 7);
    const uint32_t cA = ((lane >> 4) & 1) << 4;           // byte col offset
    const int laneB_row = (((lane >> 4) & 1) << 3) + (lane & 7);
    const uint32_t cB = ((lane >> 3) & 1) << 4;
    const uint32_t xorv = (uint32_t)(lane & 7) << 4;
    const uint32_t aRow = (uint32_t)(wy * 32 + laneA_row) * 128;
    const uint32_t bRow = (uint32_t)(wx * 64 + laneB_row) * 128;

    if (tid == 0) { MBARRIER_INIT(mb0, 1); MBARRIER_INIT(mb0 + 8, 1); }
    __syncthreads();

    float acc[2][8][4];
#pragma unroll
    for (int mi = 0; mi < 2; ++mi)
#pragma unroll
        for (int ni = 0; ni < 8; ++ni)
#pragma unroll
            for (int j = 0; j < 4; ++j) acc[mi][ni][j] = 0.f;

    // producer: issue chunk c into stage s
    auto issue = [&](int c, int s) {
        const uint32_t sb = smb + (uint32_t)s * STAGE_BYTES;
        const size_t kc = (size_t)(kcB + c);
        const size_t aOff = ((size_t)mTile * nkTot + kc) * A_TILE_ELS;
        const size_t bOff = ((size_t)nTile * nkTot + kc) * B_TILE_ELS;
        MBARRIER_EXPECT_TX(mb0 + 8 * s, STAGE_BYTES);
        bulk_g2s(sb,           Ah + aOff, 32768, mb0 + 8 * s);
        bulk_g2s(sb + OFF_AL,  Al + aOff, 32768, mb0 + 8 * s);
        bulk_g2s(sb + OFF_BH,  Bh + bOff, 16384, mb0 + 8 * s);
        bulk_g2s(sb + OFF_BL,  Bl + bOff, 16384, mb0 + 8 * s);
    };

    if (tid == 0) issue(0, 0);

    for (int c = 0; c < nkPer; ++c) {
        const int s = c & 1;
        if (tid == 0 && c + 1 < nkPer) issue(c + 1, s ^ 1);
        mbar_wait(mb0 + 8 * s, (uint32_t)((c >> 1) & 1));

        const uint32_t sb = smb + (uint32_t)s * STAGE_BYTES;
#pragma unroll
        for (int kk = 0; kk < 4; ++kk) {
            const uint32_t colA = ((uint32_t)(kk * 32) + cA) ^ xorv;
            const uint32_t colB = ((uint32_t)(kk * 32) + cB) ^ xorv;
            uint32_t ah[2][4], al[2][4];
#pragma unroll
            for (int mi = 0; mi < 2; ++mi) {
                const uint32_t mo = (uint32_t)(mi * 16 * 128);
                ldmat_x4(ah[mi], sb + aRow + mo + colA);
                ldmat_x4(al[mi], sb + OFF_AL + aRow + mo + colA);
            }
#pragma unroll
            for (int nip = 0; nip < 4; ++nip) {
                const uint32_t no = (uint32_t)(nip * 16 * 128);
                uint32_t bh[4], bl[4];
                ldmat_x4(bh, sb + OFF_BH + bRow + no + colB);
                ldmat_x4(bl, sb + OFF_BL + bRow + no + colB);
#pragma unroll
                for (int mi = 0; mi < 2; ++mi) {
                    mma16816(acc[mi][2 * nip],     ah[mi], bh);
                    mma16816(acc[mi][2 * nip],     al[mi], bh);
                    mma16816(acc[mi][2 * nip],     ah[mi], bl);
                    mma16816(acc[mi][2 * nip + 1], ah[mi], bh + 2);
                    mma16816(acc[mi][2 * nip + 1], al[mi], bh + 2);
                    mma16816(acc[mi][2 * nip + 1], ah[mi], bl + 2);
                }
            }
        }
        __syncthreads();
    }

    // epilogue
#pragma unroll
    for (int mi = 0; mi < 2; ++mi) {
        const int row = mTile * 256 + wy * 32 + mi * 16 + g;
#pragma unroll
        for (int ni = 0; ni < 8; ++ni) {
            const int col = nTile * 128 + wx * 64 + ni * 8 + q2;
            if (col < Nvalid) {
                *(float2*)&C[(size_t)row * ldc + col] =
                    make_float2(acc[mi][ni][0], acc[mi][ni][1]);
                *(float2*)&C[(size_t)(row + 8) * ldc + col] =
                    make_float2(acc[mi][ni][2], acc[mi][ni][3]);
            }
        }
    }
    __syncthreads();
    if (tid == 0) { MBARRIER_INVAL(mb0); MBARRIER_INVAL(mb0 + 8); }
}

// ---------------------------------------------------------------------------
// reduce split-K partials: g_proj = sum_z g_projp[z]
// ---------------------------------------------------------------------------
__global__ void reduce_proj_kernel() {
    const size_t i = (size_t)blockIdx.x * blockDim.x + threadIdx.x;
    if (i >= (size_t)MROWS * NPROJ) return;
    float s = 0.f;
#pragma unroll
    for (int z = 0; z < KSPLIT; ++z)
        s += g_projp[(size_t)z * MROWS * NPROJ + i];
    g_proj[i] = s;
}

// ---------------------------------------------------------------------------
// x -> tiled/swizzled bf16 hi/lo  ([16 mtiles][16 kc][256][64])
// ---------------------------------------------------------------------------
__global__ void split_x_kernel(const float* __restrict__ x)
{
    const size_t idx = (size_t)blockIdx.x * blockDim.x + threadIdx.x;
    if (idx >= (size_t)MROWS * DM) return;
    const int m = (int)(idx / DM), k = (int)(idx % DM);
    const float v = x[idx];
    const __nv_bfloat16 h = __float2bfloat16(v);
    const __nv_bfloat16 l = __float2bfloat16(v - __bfloat162float(h));
    const size_t tile = (size_t)(m >> 8) * NKC_DM + (k >> 6);
    const uint32_t off = (uint32_t)((m & 255) * 128) + ((uint32_t)((k & 63) * 2) ^ ((uint32_t)(m & 7) << 4));
    *(__nv_bfloat16*)((char*)gx_h + tile * 32768 + off) = h;
    *(__nv_bfloat16*)((char*)gx_l + tile * 32768 + off) = l;
}

// ---------------------------------------------------------------------------
// weight transpose+split: src [K][N] fp32 -> tiled B arrays [ntile][nkTot][128][64]
// ---------------------------------------------------------------------------
__global__ __launch_bounds__(1024) void tsplit_kernel(
    const float* __restrict__ src, __nv_bfloat16* __restrict__ hi,
    __nv_bfloat16* __restrict__ lo, int K, int N, int nkTot)
{
    __shared__ float tile[32][33];
    const int n0 = blockIdx.x * 32, k0 = blockIdx.y * 32;
    const int tx = threadIdx.x & 31, ty = threadIdx.x >> 5;
    tile[ty][tx] = src[(size_t)(k0 + ty) * N + n0 + tx];
    __syncthreads();
    const int k = k0 + tx, n = n0 + ty;
    const float v = tile[tx][ty];
    const __nv_bfloat16 h = __float2bfloat16(v);
    const __nv_bfloat16 l = __float2bfloat16(v - __bfloat162float(h));
    const size_t t = (size_t)(n >> 7) * nkTot + (k >> 6);
    const uint32_t off = (uint32_t)((n & 127) * 128) + ((uint32_t)((k & 63) * 2) ^ ((uint32_t)(n & 7) << 4));
    *(__nv_bfloat16*)((char*)hi + t * 16384 + off) = h;
    *(__nv_bfloat16*)((char*)lo + t * 16384 + off) = l;
}

// ---------------------------------------------------------------------------
// Causal conv1d (k=4) + SiLU; writes fp32 uc + tiled bf16 hi/lo
// ---------------------------------------------------------------------------
__global__ void conv_silu_kernel(const float* __restrict__ cw,
                                 const float* __restrict__ cb)
{
    const size_t idx = (size_t)blockIdx.x * blockDim.x + threadIdx.x;
    if (idx >= (size_t)MROWS * DI) return;
    const int d = (int)(idx % DI);
    const int m = (int)(idx / DI);
    const int t = m % TLEN;

    float acc = cb[d];
#pragma unroll
    for (int k = 0; k < 4; k++) {
        const int tt = t - 3 + k;
        if (tt >= 0)
            acc += g_uz[(size_t)(m - 3 + k) * (2 * DI) + d] * cw[d * 4 + k];
    }
    const float v = acc / (1.f + __expf(-acc));
    g_uc[idx] = v;
    const __nv_bfloat16 h = __float2bfloat16(v);
    const __nv_bfloat16 l = __float2bfloat16(v - __bfloat162float(h));
    const size_t tile = (size_t)(m >> 8) * NKC_DI + (d >> 6);
    const uint32_t off = (uint32_t)((m & 255) * 128) + ((uint32_t)((d & 63) * 2) ^ ((uint32_t)(m & 7) << 4));
    *(__nv_bfloat16*)((char*)guc_h + tile * 32768 + off) = h;
    *(__nv_bfloat16*)((char*)guc_l + tile * 32768 + off) = l;
}

// ---------------------------------------------------------------------------
// delta = softplus(proj[:, :64] @ W_dt + b_dt)
// ---------------------------------------------------------------------------
#define DT_TM 8
__global__ __launch_bounds__(256) void dt_softplus_kernel(
    const float* __restrict__ W_dt, const float* __restrict__ b_dt)
{
    __shared__ float sp[DT_TM][DTR];
    const int m0 = blockIdx.y * DT_TM;
    const int d = blockIdx.x * 256 + threadIdx.x;

    for (int i = threadIdx.x; i < DT_TM * DTR; i += 256)
        sp[i / DTR][i % DTR] = g_proj[(size_t)(m0 + i / DTR) * NPROJ + (i % DTR)];
    __syncthreads();

    const float bb = b_dt[d];
    float acc[DT_TM];
#pragma unroll
    for (int i = 0; i < DT_TM; i++) acc[i] = bb;

#pragma unroll 8
    for (int r = 0; r < DTR; r++) {
        const float w = W_dt[(size_t)r * DI + d];
#pragma unroll
        for (int i = 0; i < DT_TM; i++) acc[i] += sp[i][r] * w;
    }
#pragma unroll
    for (int i = 0; i < DT_TM; i++) {
        const float x = acc[i];
        g_delta[(size_t)(m0 + i) * DI + d] =
            fmaxf(x, 0.f) + log1pf(__expf(-fabsf(x)));
    }
}

// ---------------------------------------------------------------------------
// SSM scan, smem-tiled; epilogue writes tiled bf16 hi/lo of gated output
// ---------------------------------------------------------------------------
#define SCAN_TB 64
__global__ __launch_bounds__(256) void scan_kernel(
    const float* __restrict__ A_log, const float* __restrict__ Dp)
{
    const int b = blockIdx.y;
    const int tid = threadIdx.x;
    const int warp = tid >> 5;
    const int lane = tid & 31;
    const int d_sub = lane >> 3;
    const int n = lane & 7;
    const int d_local = warp * 4 + d_sub;
    const int d0 = blockIdx.x * 32;
    const int d = d0 + d_local;

    __shared__ float sDelta[SCAN_TB][33];
    __shared__ float sUc[SCAN_TB][33];
    __shared__ float sZ[SCAN_TB][33];
    __shared__ float sY[SCAN_TB][33];
    __shared__ float sB[SCAN_TB][NST];
    __shared__ float sC[SCAN_TB][NST];
    __shared__ float sD[32];

    if (tid < 32) sD[tid] = Dp[d0 + tid];

    const float A0 = -__expf(A_log[(size_t)d * NST + n]);
    const float A1 = -__expf(A_log[(size_t)d * NST + n + 8]);

    float h0 = 0.f, h1 = 0.f;

    for (int t0 = 0; t0 < TLEN; t0 += SCAN_TB) {
        __syncthreads();
#pragma unroll
        for (int p = 0; p < 8; ++p) {
            const int i = tid + p * 256;
            const int r = i >> 5, c = i & 31;
            const size_t row = (size_t)(b * TLEN + t0 + r);
            sDelta[r][c] = g_delta[row * DI + d0 + c];
            sUc[r][c]    = g_uc[row * DI + d0 + c];
            sZ[r][c]     = g_uz[row * (2 * DI) + DI + d0 + c];
            const float v = g_proj[row * NPROJ + DTR + c];
            if (c < NST) sB[r][c] = v;
            else         sC[r][c - NST] = v;
        }
        __syncthreads();

#pragma unroll 4
        for (int tt = 0; tt < SCAN_TB; ++tt) {
            const float delta = sDelta[tt][d_local];
            const float du = delta * sUc[tt][d_local];
            h0 = __expf(delta * A0) * h0 + du * sB[tt][n];
            h1 = __expf(delta * A1) * h1 + du * sB[tt][n + 8];
            float y = h0 * sC[tt][n] + h1 * sC[tt][n + 8];
            y += __shfl_xor_sync(0xffffffffu, y, 1);
            y += __shfl_xor_sync(0xffffffffu, y, 2);
            y += __shfl_xor_sync(0xffffffffu, y, 4);
            if (n == 0) sY[tt][d_local] = y;
        }
        __syncthreads();

#pragma unroll
        for (int p = 0; p < 8; ++p) {
            const int i = tid + p * 256;
            const int r = i >> 5, c = i & 31;
            const float uc = sUc[r][c];
            const float z = sZ[r][c];
            const float gate = z / (1.f + __expf(-z));
            const float v = (sY[r][c] + uc * sD[c]) * gate;
            const int m = b * TLEN + t0 + r;
            const int dd = d0 + c;
            const __nv_bfloat16 h = __float2bfloat16(v);
            const __nv_bfloat16 l = __float2bfloat16(v - __bfloat162float(h));
            const size_t tile = (size_t)(m >> 8) * NKC_DI + (dd >> 6);
            const uint32_t off = (uint32_t)((m & 255) * 128) +
                ((uint32_t)((dd & 63) * 2) ^ ((uint32_t)(m & 7) << 4));
            *(__nv_bfloat16*)((char*)gy_h + tile * 32768 + off) = h;
            *(__nv_bfloat16*)((char*)gy_l + tile * 32768 + off) = l;
        }
    }
}

// ---------------------------------------------------------------------------
extern "C" void kernel_launch(void* const* d_in, const int* in_sizes, int n_in,
                              void* d_out, int out_size)
{
    const float* x      = (const float*)d_in[0];
    const float* W_in   = (const float*)d_in[1];
    const float* conv_w = (const float*)d_in[2];
    const float* conv_b = (const float*)d_in[3];
    const float* W_xprj = (const float*)d_in[4];
    const float* W_dt   = (const float*)d_in[5];
    const float* b_dt   = (const float*)d_in[6];
    const float* A_log  = (const float*)d_in[7];
    const float* Dp     = (const float*)d_in[8];
    const float* W_out  = (const float*)d_in[9];
    float* out = (float*)d_out;

    cudaFuncSetAttribute(tgemm_bulk, cudaFuncAttributeMaxDynamicSharedMemorySize, TG_SMEM_BYTES);

    void *p_uz, *p_projp;
    void *p_xh, *p_xl, *p_WinTh, *p_WinTl, *p_uch, *p_ucl;
    void *p_WxTh, *p_WxTl, *p_yh, *p_yl, *p_WoTh, *p_WoTl;
    cudaGetSymbolAddress(&p_uz, g_uz);
    cudaGetSymbolAddress(&p_projp, g_projp);
    cudaGetSymbolAddress(&p_xh, gx_h);       cudaGetSymbolAddress(&p_xl, gx_l);
    cudaGetSymbolAddress(&p_WinTh, gWinT_h); cudaGetSymbolAddress(&p_WinTl, gWinT_l);
    cudaGetSymbolAddress(&p_uch, guc_h);     cudaGetSymbolAddress(&p_ucl, guc_l);
    cudaGetSymbolAddress(&p_WxTh, gWxT_h);   cudaGetSymbolAddress(&p_WxTl, gWxT_l);
    cudaGetSymbolAddress(&p_yh, gy_h);       cudaGetSymbolAddress(&p_yl, gy_l);
    cudaGetSymbolAddress(&p_WoTh, gWoT_h);   cudaGetSymbolAddress(&p_WoTl, gWoT_l);

    // operand prep (tiled + swizzled)
    {
        size_t n = (size_t)MROWS * DM;
        split_x_kernel<<<(unsigned)((n + 255) / 256), 256>>>(x);
    }
    tsplit_kernel<<<dim3((2 * DI) / 32, DM / 32), 1024>>>(
        W_in, (__nv_bfloat16*)p_WinTh, (__nv_bfloat16*)p_WinTl, DM, 2 * DI, NKC_DM);
    tsplit_kernel<<<dim3(NPROJ / 32, DI / 32), 1024>>>(
        W_xprj, (__nv_bfloat16*)p_WxTh, (__nv_bfloat16*)p_WxTl, DI, NPROJ, NKC_DI);
    tsplit_kernel<<<dim3(DM / 32, DI / 32), 1024>>>(
        W_out, (__nv_bfloat16*)p_WoTh, (__nv_bfloat16*)p_WoTl, DI, DM, NKC_DI);

    // 1) xz = x @ W_in : M=4096 K=1024 N=4096
    tgemm_bulk<<<dim3(32, 16, 1), 512, TG_SMEM_BYTES>>>(
        (const __nv_bfloat16*)p_xh, (const __nv_bfloat16*)p_xl,
        (const __nv_bfloat16*)p_WinTh, (const __nv_bfloat16*)p_WinTl,
        (float*)p_uz, 2 * DI, 2 * DI, NKC_DM, NKC_DM, 0);

    // 2) conv + SiLU (+ tiled bf16 split)
    {
        const size_t total = (size_t)MROWS * DI;
        conv_silu_kernel<<<(unsigned)((total + 255) / 256), 256>>>(conv_w, conv_b);
    }

    // 3) proj = uc @ W_xproj : split-K=8 (4 chunks each) -> partials -> reduce
    tgemm_bulk<<<dim3(1, 16, KSPLIT), 512, TG_SMEM_BYTES>>>(
        (const __nv_bfloat16*)p_uch, (const __nv_bfloat16*)p_ucl,
        (const __nv_bfloat16*)p_WxTh, (const __nv_bfloat16*)p_WxTl,
        (float*)p_projp, NPROJ, NPROJ, NKC_DI, NKC_DI / KSPLIT,
        (size_t)MROWS * NPROJ);
    {
        const size_t total = (size_t)MROWS * NPROJ;
        reduce_proj_kernel<<<(unsigned)((total + 255) / 256), 256>>>();
    }

    // 4) delta
    dt_softplus_kernel<<<dim3(DI / 256, MROWS / DT_TM), 256>>>(W_dt, b_dt);

    // 5) scan
    scan_kernel<<<dim3(DI / 32, BSZ), 256>>>(A_log, Dp);

    // 6) out = y @ W_out : M=4096 K=2048 N=1024
    tgemm_bulk<<<dim3(8, 16, 1), 512, TG_SMEM_BYTES>>>(
        (const __nv_bfloat16*)p_yh, (const __nv_bfloat16*)p_yl,
        (const __nv_bfloat16*)p_WoTh, (const __nv_bfloat16*)p_WoTl,
        out, DM, DM, NKC_DI, NKC_DI, 0);
}

// round 8
// speedup vs baseline: 1.5844x; 1.5844x over previous
#include <cuda_runtime.h>
#include <cuda_bf16.h>
#include <cstdint>
#include <math.h>

// Problem constants
#define BSZ   2
#define TLEN  2048
#define DM    1024
#define DI    2048
#define NST   16
#define DTR   64
#define NPROJ 96
#define MROWS (BSZ*TLEN)    // 4096
#define KSPLIT 8

#define NKC_DM (DM/32)      // 32 k-chunks for K=1024
#define NKC_DI (DI/32)      // 64 k-chunks for K=2048

// Tiles: 128 rows x 32 k bf16 = 8KB, SW64-swizzled 64B rows, stored contiguously.
#define TILE_BYTES 8192
#define STAGE_BYTES (4*TILE_BYTES)     // Ah|Al|Bh|Bl = 32KB
#define NSTAGE 3
#define TG_SMEM_BYTES (NSTAGE*STAGE_BYTES)  // 96KB

#define OFF_AL TILE_BYTES
#define OFF_BH (2*TILE_BYTES)
#define OFF_BL (3*TILE_BYTES)

// ---------------------------------------------------------------------------
// Scratch (device globals; zero-initialized — WxT pad rows stay zero)
// ---------------------------------------------------------------------------
__device__ __align__(256) float g_uz[(size_t)MROWS * 2 * DI];
__device__ __align__(256) float g_uc[(size_t)MROWS * DI];
__device__ __align__(256) float g_proj[(size_t)MROWS * NPROJ];
__device__ __align__(256) float g_projp[(size_t)KSPLIT * MROWS * NPROJ];
__device__ __align__(256) float g_delta[(size_t)MROWS * DI];

// pre-tiled, pre-swizzled bf16 operands: [tile][128 rows][32 k] (8KB tiles)
__device__ __align__(256) __nv_bfloat16 gx_h[(size_t)MROWS * DM];      // [32 mt][32 kc]
__device__ __align__(256) __nv_bfloat16 gx_l[(size_t)MROWS * DM];
__device__ __align__(256) __nv_bfloat16 gWinT_h[(size_t)(2*DI) * DM];  // [32 nt][32 kc]
__device__ __align__(256) __nv_bfloat16 gWinT_l[(size_t)(2*DI) * DM];
__device__ __align__(256) __nv_bfloat16 guc_h[(size_t)MROWS * DI];     // [32 mt][64 kc]
__device__ __align__(256) __nv_bfloat16 guc_l[(size_t)MROWS * DI];
__device__ __align__(256) __nv_bfloat16 gWxT_h[(size_t)128 * DI];      // [1 nt][64 kc] rows 96..127 zero
__device__ __align__(256) __nv_bfloat16 gWxT_l[(size_t)128 * DI];
__device__ __align__(256) __nv_bfloat16 gy_h[(size_t)MROWS * DI];      // [32 mt][64 kc]
__device__ __align__(256) __nv_bfloat16 gy_l[(size_t)MROWS * DI];
__device__ __align__(256) __nv_bfloat16 gWoT_h[(size_t)DM * DI];       // [8 nt][64 kc]
__device__ __align__(256) __nv_bfloat16 gWoT_l[(size_t)DM * DI];

// ---------------------------------------------------------------------------
// PTX helpers (sm_90 BASELINE only)
// ---------------------------------------------------------------------------
__device__ __forceinline__ uint32_t smem_u32(const void* p) {
    uint32_t a;
    asm("{ .reg .u64 t; cvta.to.shared.u64 t, %1; cvt.u32.u64 %0, t; }"
        : "=r"(a) : "l"(p));
    return a;
}
__device__ __forceinline__ void bulk_g2s(uint32_t dst, const void* src,
                                         uint32_t bytes, uint32_t mbar) {
    asm volatile(
        "cp.async.bulk.shared::cta.global.mbarrier::complete_tx::bytes "
        "[%0], [%1], %2, [%3];"
        :: "r"(dst), "l"(src), "r"(bytes), "r"(mbar) : "memory");
}
#define MBARRIER_INIT(mb, c) \
    asm volatile("mbarrier.init.shared.b64 [%0], %1;" :: "r"((uint32_t)(mb)), "r"((uint32_t)(c)) : "memory")
#define MBARRIER_INVAL(mb) \
    asm volatile("mbarrier.inval.shared.b64 [%0];" :: "r"((uint32_t)(mb)) : "memory")
#define MBARRIER_EXPECT_TX(mb, tx) \
    asm volatile("mbarrier.arrive.expect_tx.shared.b64 _, [%0], %1;" :: "r"((uint32_t)(mb)), "r"((uint32_t)(tx)) : "memory")

__device__ __forceinline__ void mbar_wait(uint32_t mb, uint32_t parity) {
    uint32_t done;
    asm volatile("{\n\t.reg .pred p;\n\t"
                 "mbarrier.try_wait.parity.acquire.cta.shared::cta.b64 p, [%1], %2;\n\t"
                 "selp.b32 %0, 1, 0, p;\n\t}"
                 : "=r"(done) : "r"(mb), "r"(parity) : "memory");
    if (!done) {
        asm volatile("{\n\t.reg .pred P1;\n\t"
                     "W%=:\n\t"
                     "mbarrier.try_wait.parity.acquire.cta.shared::cta.b64 P1, [%0], %1, 0x989680;\n\t"
                     "@P1 bra.uni D%=;\n\t"
                     "bra.uni W%=;\n\t"
                     "D%=:\n\t}" :: "r"(mb), "r"(parity) : "memory");
    }
}
__device__ __forceinline__ void ldmat_x4(uint32_t* r, uint32_t addr) {
    asm volatile("ldmatrix.sync.aligned.m8n8.x4.shared.b16 {%0,%1,%2,%3}, [%4];"
        : "=r"(r[0]), "=r"(r[1]), "=r"(r[2]), "=r"(r[3]) : "r"(addr));
}
__device__ __forceinline__ void mma16816(float* c, const uint32_t* a, const uint32_t* b) {
    asm volatile(
        "mma.sync.aligned.m16n8k16.row.col.f32.bf16.bf16.f32 "
        "{%0,%1,%2,%3}, {%4,%5,%6,%7}, {%8,%9}, {%0,%1,%2,%3};"
        : "+f"(c[0]), "+f"(c[1]), "+f"(c[2]), "+f"(c[3])
        : "r"(a[0]), "r"(a[1]), "r"(a[2]), "r"(a[3]), "r"(b[0]), "r"(b[1]));
}

// SW64 swizzle for (row, k) inside a 128x32 tile, byte offset
__device__ __forceinline__ uint32_t tile_off(int row, int k) {
    return (uint32_t)(row * 64) + (((uint32_t)(k * 2)) ^ (((uint32_t)(row >> 1) & 3u) << 4));
}

// ---------------------------------------------------------------------------
// bf16 3-split HMMA GEMM, bulk-copy pipeline, occupancy 2.
// CTA tile 128x128, BK=32, 256 threads (8 warps: 4 M x 2 N), warp tile 32x64.
// 3-stage pipeline, producer 2 ahead. Operands pre-tiled/swizzled in gmem.
// ---------------------------------------------------------------------------
__global__ __launch_bounds__(256, 2) void tgemm_bulk(
    const __nv_bfloat16* __restrict__ Ah, const __nv_bfloat16* __restrict__ Al,
    const __nv_bfloat16* __restrict__ Bh, const __nv_bfloat16* __restrict__ Bl,
    float* __restrict__ C, int ldc, int Nvalid, int nkTot, int nkPer, size_t cslice)
{
    extern __shared__ char sm[];
    __shared__ uint64_t mbars[NSTAGE];
    const uint32_t smb = smem_u32(sm);
    const uint32_t mb0 = smem_u32(&mbars[0]);

    const int tid = threadIdx.x;
    const int wid = tid >> 5, lane = tid & 31;
    const int wy = wid & 3, wx = wid >> 2;       // 4 (M) x 2 (N)
    const int g = lane >> 2, q2 = (lane & 3) * 2;
    const int mTile = blockIdx.y, nTile = blockIdx.x;
    const int kcB = blockIdx.z * nkPer;
    C += (size_t)blockIdx.z * cslice;

    // fragment ldmatrix lane addressing (SW64 rows of 64B)
    const int laneA_row = (((lane >> 3) & 1) << 3) + (lane & 7);      // 0..15
    const uint32_t cA = ((lane >> 4) & 1) << 4;                       // {0,16}
    const uint32_t xorA = (((uint32_t)(laneA_row >> 1)) & 3u) << 4;
    const int laneB_row = (((lane >> 4) & 1) << 3) + (lane & 7);
    const uint32_t cB = ((lane >> 3) & 1) << 4;
    const uint32_t xorB = (((uint32_t)(laneB_row >> 1)) & 3u) << 4;
    const uint32_t aRow = (uint32_t)(wy * 32 + laneA_row) * 64;
    const uint32_t bRow = (uint32_t)(wx * 64 + laneB_row) * 64;

    if (tid == 0) {
#pragma unroll
        for (int s = 0; s < NSTAGE; ++s) MBARRIER_INIT(mb0 + 8 * s, 1);
    }
    __syncthreads();

    float acc[2][8][4];
#pragma unroll
    for (int mi = 0; mi < 2; ++mi)
#pragma unroll
        for (int ni = 0; ni < 8; ++ni)
#pragma unroll
            for (int j = 0; j < 4; ++j) acc[mi][ni][j] = 0.f;

    auto issue = [&](int c, int s) {
        const uint32_t sb = smb + (uint32_t)s * STAGE_BYTES;
        const uint32_t mb = mb0 + 8 * s;
        const size_t kc = (size_t)(kcB + c);
        const size_t aOff = ((size_t)mTile * nkTot + kc) * (TILE_BYTES / 2);
        const size_t bOff = ((size_t)nTile * nkTot + kc) * (TILE_BYTES / 2);
        MBARRIER_EXPECT_TX(mb, STAGE_BYTES);
        bulk_g2s(sb,          Ah + aOff, TILE_BYTES, mb);
        bulk_g2s(sb + OFF_AL, Al + aOff, TILE_BYTES, mb);
        bulk_g2s(sb + OFF_BH, Bh + bOff, TILE_BYTES, mb);
        bulk_g2s(sb + OFF_BL, Bl + bOff, TILE_BYTES, mb);
    };

    if (tid == 0) {
        issue(0, 0);
        if (nkPer > 1) issue(1, 1);
    }

    for (int c = 0; c < nkPer; ++c) {
        const int st = c % NSTAGE;
        if (tid == 0 && c + 2 < nkPer) issue(c + 2, (c + 2) % NSTAGE);
        mbar_wait(mb0 + 8 * st, (uint32_t)((c / NSTAGE) & 1));

        const uint32_t sb = smb + (uint32_t)st * STAGE_BYTES;
#pragma unroll
        for (int kk = 0; kk < 2; ++kk) {
            const uint32_t colA = ((uint32_t)(kk * 32) + cA) ^ xorA;
            const uint32_t colB = ((uint32_t)(kk * 32) + cB) ^ xorB;
            uint32_t ah[2][4], al[2][4];
#pragma unroll
            for (int mi = 0; mi < 2; ++mi) {
                const uint32_t mo = (uint32_t)(mi * 16 * 64);
                ldmat_x4(ah[mi], sb + aRow + mo + colA);
                ldmat_x4(al[mi], sb + OFF_AL + aRow + mo + colA);
            }
#pragma unroll
            for (int nip = 0; nip < 4; ++nip) {
                const uint32_t no = (uint32_t)(nip * 16 * 64);
                uint32_t bh[4], bl[4];
                ldmat_x4(bh, sb + OFF_BH + bRow + no + colB);
                ldmat_x4(bl, sb + OFF_BL + bRow + no + colB);
#pragma unroll
                for (int mi = 0; mi < 2; ++mi) {
                    mma16816(acc[mi][2 * nip],     ah[mi], bh);
                    mma16816(acc[mi][2 * nip],     al[mi], bh);
                    mma16816(acc[mi][2 * nip],     ah[mi], bl);
                    mma16816(acc[mi][2 * nip + 1], ah[mi], bh + 2);
                    mma16816(acc[mi][2 * nip + 1], al[mi], bh + 2);
                    mma16816(acc[mi][2 * nip + 1], ah[mi], bl + 2);
                }
            }
        }
        __syncthreads();
    }

    // epilogue
#pragma unroll
    for (int mi = 0; mi < 2; ++mi) {
        const int row = mTile * 128 + wy * 32 + mi * 16 + g;
#pragma unroll
        for (int ni = 0; ni < 8; ++ni) {
            const int col = nTile * 128 + wx * 64 + ni * 8 + q2;
            if (col < Nvalid) {
                *(float2*)&C[(size_t)row * ldc + col] =
                    make_float2(acc[mi][ni][0], acc[mi][ni][1]);
                *(float2*)&C[(size_t)(row + 8) * ldc + col] =
                    make_float2(acc[mi][ni][2], acc[mi][ni][3]);
            }
        }
    }
    __syncthreads();
    if (tid == 0) {
#pragma unroll
        for (int s = 0; s < NSTAGE; ++s) MBARRIER_INVAL(mb0 + 8 * s);
    }
}

// ---------------------------------------------------------------------------
// reduce split-K partials
// ---------------------------------------------------------------------------
__global__ void reduce_proj_kernel() {
    const size_t i = (size_t)blockIdx.x * blockDim.x + threadIdx.x;
    if (i >= (size_t)MROWS * NPROJ) return;
    float s = 0.f;
#pragma unroll
    for (int z = 0; z < KSPLIT; ++z)
        s += g_projp[(size_t)z * MROWS * NPROJ + i];
    g_proj[i] = s;
}

// ---------------------------------------------------------------------------
// x -> tiled/swizzled bf16 hi/lo  ([32 mt][32 kc][128][32])
// ---------------------------------------------------------------------------
__global__ void split_x_kernel(const float* __restrict__ x)
{
    const size_t idx = (size_t)blockIdx.x * blockDim.x + threadIdx.x;
    if (idx >= (size_t)MROWS * DM) return;
    const int m = (int)(idx / DM), k = (int)(idx % DM);
    const float v = x[idx];
    const __nv_bfloat16 h = __float2bfloat16(v);
    const __nv_bfloat16 l = __float2bfloat16(v - __bfloat162float(h));
    const size_t tile = (size_t)(m >> 7) * NKC_DM + (k >> 5);
    const uint32_t off = tile_off(m & 127, k & 31);
    *(__nv_bfloat16*)((char*)gx_h + tile * TILE_BYTES + off) = h;
    *(__nv_bfloat16*)((char*)gx_l + tile * TILE_BYTES + off) = l;
}

// ---------------------------------------------------------------------------
// weight transpose+split: src [K][N] fp32 -> [nt][nkTot][128][32]
// ---------------------------------------------------------------------------
__global__ __launch_bounds__(1024) void tsplit_kernel(
    const float* __restrict__ src, __nv_bfloat16* __restrict__ hi,
    __nv_bfloat16* __restrict__ lo, int K, int N, int nkTot)
{
    __shared__ float tile[32][33];
    const int n0 = blockIdx.x * 32, k0 = blockIdx.y * 32;
    const int tx = threadIdx.x & 31, ty = threadIdx.x >> 5;
    tile[ty][tx] = src[(size_t)(k0 + ty) * N + n0 + tx];
    __syncthreads();
    const int k = k0 + tx, n = n0 + ty;
    const float v = tile[tx][ty];
    const __nv_bfloat16 h = __float2bfloat16(v);
    const __nv_bfloat16 l = __float2bfloat16(v - __bfloat162float(h));
    const size_t t = (size_t)(n >> 7) * nkTot + (k >> 5);
    const uint32_t off = tile_off(n & 127, k & 31);
    *(__nv_bfloat16*)((char*)hi + t * TILE_BYTES + off) = h;
    *(__nv_bfloat16*)((char*)lo + t * TILE_BYTES + off) = l;
}

// ---------------------------------------------------------------------------
// Causal conv1d (k=4) + SiLU; fp32 uc + tiled bf16 hi/lo
// ---------------------------------------------------------------------------
__global__ void conv_silu_kernel(const float* __restrict__ cw,
                                 const float* __restrict__ cb)
{
    const size_t idx = (size_t)blockIdx.x * blockDim.x + threadIdx.x;
    if (idx >= (size_t)MROWS * DI) return;
    const int d = (int)(idx % DI);
    const int m = (int)(idx / DI);
    const int t = m % TLEN;

    float acc = cb[d];
#pragma unroll
    for (int k = 0; k < 4; k++) {
        const int tt = t - 3 + k;
        if (tt >= 0)
            acc += g_uz[(size_t)(m - 3 + k) * (2 * DI) + d] * cw[d * 4 + k];
    }
    const float v = acc / (1.f + __expf(-acc));
    g_uc[idx] = v;
    const __nv_bfloat16 h = __float2bfloat16(v);
    const __nv_bfloat16 l = __float2bfloat16(v - __bfloat162float(h));
    const size_t tile = (size_t)(m >> 7) * NKC_DI + (d >> 5);
    const uint32_t off = tile_off(m & 127, d & 31);
    *(__nv_bfloat16*)((char*)guc_h + tile * TILE_BYTES + off) = h;
    *(__nv_bfloat16*)((char*)guc_l + tile * TILE_BYTES + off) = l;
}

// ---------------------------------------------------------------------------
// delta = softplus(proj[:, :64] @ W_dt + b_dt)
// ---------------------------------------------------------------------------
#define DT_TM 8
__global__ __launch_bounds__(256) void dt_softplus_kernel(
    const float* __restrict__ W_dt, const float* __restrict__ b_dt)
{
    __shared__ float sp[DT_TM][DTR];
    const int m0 = blockIdx.y * DT_TM;
    const int d = blockIdx.x * 256 + threadIdx.x;

    for (int i = threadIdx.x; i < DT_TM * DTR; i += 256)
        sp[i / DTR][i % DTR] = g_proj[(size_t)(m0 + i / DTR) * NPROJ + (i % DTR)];
    __syncthreads();

    const float bb = b_dt[d];
    float acc[DT_TM];
#pragma unroll
    for (int i = 0; i < DT_TM; i++) acc[i] = bb;

#pragma unroll 8
    for (int r = 0; r < DTR; r++) {
        const float w = W_dt[(size_t)r * DI + d];
#pragma unroll
        for (int i = 0; i < DT_TM; i++) acc[i] += sp[i][r] * w;
    }
#pragma unroll
    for (int i = 0; i < DT_TM; i++) {
        const float x = acc[i];
        g_delta[(size_t)(m0 + i) * DI + d] =
            fmaxf(x, 0.f) + log1pf(__expf(-fabsf(x)));
    }
}

// ---------------------------------------------------------------------------
// SSM scan, smem-tiled; epilogue writes tiled bf16 hi/lo of gated output
// ---------------------------------------------------------------------------
#define SCAN_TB 64
__global__ __launch_bounds__(256) void scan_kernel(
    const float* __restrict__ A_log, const float* __restrict__ Dp)
{
    const int b = blockIdx.y;
    const int tid = threadIdx.x;
    const int warp = tid >> 5;
    const int lane = tid & 31;
    const int d_sub = lane >> 3;
    const int n = lane & 7;
    const int d_local = warp * 4 + d_sub;
    const int d0 = blockIdx.x * 32;
    const int d = d0 + d_local;

    __shared__ float sDelta[SCAN_TB][33];
    __shared__ float sUc[SCAN_TB][33];
    __shared__ float sZ[SCAN_TB][33];
    __shared__ float sY[SCAN_TB][33];
    __shared__ float sB[SCAN_TB][NST];
    __shared__ float sC[SCAN_TB][NST];
    __shared__ float sD[32];

    if (tid < 32) sD[tid] = Dp[d0 + tid];

    const float A0 = -__expf(A_log[(size_t)d * NST + n]);
    const float A1 = -__expf(A_log[(size_t)d * NST + n + 8]);

    float h0 = 0.f, h1 = 0.f;

    for (int t0 = 0; t0 < TLEN; t0 += SCAN_TB) {
        __syncthreads();
#pragma unroll
        for (int p = 0; p < 8; ++p) {
            const int i = tid + p * 256;
            const int r = i >> 5, c = i & 31;
            const size_t row = (size_t)(b * TLEN + t0 + r);
            sDelta[r][c] = g_delta[row * DI + d0 + c];
            sUc[r][c]    = g_uc[row * DI + d0 + c];
            sZ[r][c]     = g_uz[row * (2 * DI) + DI + d0 + c];
            const float v = g_proj[row * NPROJ + DTR + c];
            if (c < NST) sB[r][c] = v;
            else         sC[r][c - NST] = v;
        }
        __syncthreads();

#pragma unroll 4
        for (int tt = 0; tt < SCAN_TB; ++tt) {
            const float delta = sDelta[tt][d_local];
            const float du = delta * sUc[tt][d_local];
            h0 = __expf(delta * A0) * h0 + du * sB[tt][n];
            h1 = __expf(delta * A1) * h1 + du * sB[tt][n + 8];
            float y = h0 * sC[tt][n] + h1 * sC[tt][n + 8];
            y += __shfl_xor_sync(0xffffffffu, y, 1);
            y += __shfl_xor_sync(0xffffffffu, y, 2);
            y += __shfl_xor_sync(0xffffffffu, y, 4);
            if (n == 0) sY[tt][d_local] = y;
        }
        __syncthreads();

#pragma unroll
        for (int p = 0; p < 8; ++p) {
            const int i = tid + p * 256;
            const int r = i >> 5, c = i & 31;
            const float uc = sUc[r][c];
            const float z = sZ[r][c];
            const float gate = z / (1.f + __expf(-z));
            const float v = (sY[r][c] + uc * sD[c]) * gate;
            const int m = b * TLEN + t0 + r;
            const int dd = d0 + c;
            const __nv_bfloat16 h = __float2bfloat16(v);
            const __nv_bfloat16 l = __float2bfloat16(v - __bfloat162float(h));
            const size_t tile = (size_t)(m >> 7) * NKC_DI + (dd >> 5);
            const uint32_t off = tile_off(m & 127, dd & 31);
            *(__nv_bfloat16*)((char*)gy_h + tile * TILE_BYTES + off) = h;
            *(__nv_bfloat16*)((char*)gy_l + tile * TILE_BYTES + off) = l;
        }
    }
}

// ---------------------------------------------------------------------------
extern "C" void kernel_launch(void* const* d_in, const int* in_sizes, int n_in,
                              void* d_out, int out_size)
{
    const float* x      = (const float*)d_in[0];
    const float* W_in   = (const float*)d_in[1];
    const float* conv_w = (const float*)d_in[2];
    const float* conv_b = (const float*)d_in[3];
    const float* W_xprj = (const float*)d_in[4];
    const float* W_dt   = (const float*)d_in[5];
    const float* b_dt   = (const float*)d_in[6];
    const float* A_log  = (const float*)d_in[7];
    const float* Dp     = (const float*)d_in[8];
    const float* W_out  = (const float*)d_in[9];
    float* out = (float*)d_out;

    cudaFuncSetAttribute(tgemm_bulk, cudaFuncAttributeMaxDynamicSharedMemorySize, TG_SMEM_BYTES);

    void *p_uz, *p_projp;
    void *p_xh, *p_xl, *p_WinTh, *p_WinTl, *p_uch, *p_ucl;
    void *p_WxTh, *p_WxTl, *p_yh, *p_yl, *p_WoTh, *p_WoTl;
    cudaGetSymbolAddress(&p_uz, g_uz);
    cudaGetSymbolAddress(&p_projp, g_projp);
    cudaGetSymbolAddress(&p_xh, gx_h);       cudaGetSymbolAddress(&p_xl, gx_l);
    cudaGetSymbolAddress(&p_WinTh, gWinT_h); cudaGetSymbolAddress(&p_WinTl, gWinT_l);
    cudaGetSymbolAddress(&p_uch, guc_h);     cudaGetSymbolAddress(&p_ucl, guc_l);
    cudaGetSymbolAddress(&p_WxTh, gWxT_h);   cudaGetSymbolAddress(&p_WxTl, gWxT_l);
    cudaGetSymbolAddress(&p_yh, gy_h);       cudaGetSymbolAddress(&p_yl, gy_l);
    cudaGetSymbolAddress(&p_WoTh, gWoT_h);   cudaGetSymbolAddress(&p_WoTl, gWoT_l);

    // operand prep (tiled + SW64-swizzled)
    {
        size_t n = (size_t)MROWS * DM;
        split_x_kernel<<<(unsigned)((n + 255) / 256), 256>>>(x);
    }
    tsplit_kernel<<<dim3((2 * DI) / 32, DM / 32), 1024>>>(
        W_in, (__nv_bfloat16*)p_WinTh, (__nv_bfloat16*)p_WinTl, DM, 2 * DI, NKC_DM);
    tsplit_kernel<<<dim3(NPROJ / 32, DI / 32), 1024>>>(
        W_xprj, (__nv_bfloat16*)p_WxTh, (__nv_bfloat16*)p_WxTl, DI, NPROJ, NKC_DI);
    tsplit_kernel<<<dim3(DM / 32, DI / 32), 1024>>>(
        W_out, (__nv_bfloat16*)p_WoTh, (__nv_bfloat16*)p_WoTl, DI, DM, NKC_DI);

    // 1) xz = x @ W_in : grid 32x32, 32 chunks
    tgemm_bulk<<<dim3(32, 32, 1), 256, TG_SMEM_BYTES>>>(
        (const __nv_bfloat16*)p_xh, (const __nv_bfloat16*)p_xl,
        (const __nv_bfloat16*)p_WinTh, (const __nv_bfloat16*)p_WinTl,
        (float*)p_uz, 2 * DI, 2 * DI, NKC_DM, NKC_DM, 0);

    // 2) conv + SiLU
    {
        const size_t total = (size_t)MROWS * DI;
        conv_silu_kernel<<<(unsigned)((total + 255) / 256), 256>>>(conv_w, conv_b);
    }

    // 3) proj = uc @ W_xproj : split-K=8 (8 chunks each)
    tgemm_bulk<<<dim3(1, 32, KSPLIT), 256, TG_SMEM_BYTES>>>(
        (const __nv_bfloat16*)p_uch, (const __nv_bfloat16*)p_ucl,
        (const __nv_bfloat16*)p_WxTh, (const __nv_bfloat16*)p_WxTl,
        (float*)p_projp, NPROJ, NPROJ, NKC_DI, NKC_DI / KSPLIT,
        (size_t)MROWS * NPROJ);
    {
        const size_t total = (size_t)MROWS * NPROJ;
        reduce_proj_kernel<<<(unsigned)((total + 255) / 256), 256>>>();
    }

    // 4) delta
    dt_softplus_kernel<<<dim3(DI / 256, MROWS / DT_TM), 256>>>(W_dt, b_dt);

    // 5) scan
    scan_kernel<<<dim3(DI / 32, BSZ), 256>>>(A_log, Dp);

    // 6) out = y @ W_out : grid 8x32, 64 chunks
    tgemm_bulk<<<dim3(8, 32, 1), 256, TG_SMEM_BYTES>>>(
        (const __nv_bfloat16*)p_yh, (const __nv_bfloat16*)p_yl,
        (const __nv_bfloat16*)p_WoTh, (const __nv_bfloat16*)p_WoTl,
        out, DM, DM, NKC_DI, NKC_DI, 0);
}